// round 1
// baseline (speedup 1.0000x reference)
#include <cuda_runtime.h>
#include <math.h>

#define N_PTS 8192
#define HDIM  512
#define NM1   8191   // N-1

// ---------------- scratch (device globals; no allocations allowed) ----------
__device__ __align__(16) float g_h0[N_PTS * HDIM];   // 16 MB
__device__ __align__(16) float g_h1[N_PTS * HDIM];   // 16 MB
__device__ float  g_y[N_PTS * 5];
__device__ float  g_dpsi[NM1 * 5];
__device__ float  g_ws[NM1];
__device__ float  g_conv[NM1 * 5];
__device__ float  g_par[6];   // alpha, beta, sigma, gamma, mu, C
__device__ double g_acc;

// ---------------- setup: params + Caputo weights + zeroing ------------------
__global__ void setup_kernel(const float* __restrict__ rb, const float* __restrict__ rs,
                             const float* __restrict__ rg, const float* __restrict__ rm,
                             const float* __restrict__ za_p) {
    int tid = threadIdx.x;
    float za    = za_p[0];
    float alpha = 0.6f + 0.4f * (1.0f / (1.0f + expf(-za)));
    if (tid == 0) {
        g_par[0] = alpha;
        g_par[1] = log1pf(expf(rb[0]));   // beta
        g_par[2] = log1pf(expf(rs[0]));   // sigma
        g_par[3] = log1pf(expf(rg[0]));   // gamma
        g_par[4] = log1pf(expf(rm[0]));   // mu
        g_par[5] = powf(0.1f, -alpha) / expf(lgammaf(2.0f - alpha));  // C
        g_acc    = 0.0;
    }
    double ex = 1.0 - (double)alpha;
    for (int r = tid; r < NM1; r += blockDim.x) {
        double w = pow((double)(r + 1), ex);
        if (r > 0) w -= pow((double)r, ex);
        g_ws[r] = (float)w;
    }
    for (int i = tid; i < NM1 * 5; i += blockDim.x) g_conv[i] = 0.0f;
}

// ---------------- layer 0: h = tanh(t * W_in + b_in), t is [N,1] ------------
__global__ void layer0_kernel(const float* __restrict__ t,
                              const float* __restrict__ W_in,
                              const float* __restrict__ b_in) {
    int idx = blockIdx.x * blockDim.x + threadIdx.x;
    if (idx >= N_PTS * HDIM) return;
    int i = idx >> 9;          // row
    int j = idx & (HDIM - 1);  // col
    g_h0[idx] = tanhf(t[i] * W_in[j] + b_in[j]);
}

// ---------------- hidden GEMM + bias + tanh: C = tanh(A@B + bias) -----------
// A: [8192,512] row-major, B: [512,512] row-major, 128x128x8 tile, 8x8/thread
__global__ __launch_bounds__(256, 2)
void gemm_tanh_kernel(const float* __restrict__ A, const float* __restrict__ B,
                      const float* __restrict__ bias, float* __restrict__ C) {
    __shared__ float As[8][128];   // transposed A tile: As[k][m]
    __shared__ float Bs[8][128];   // Bs[k][n]

    int tid = threadIdx.x;
    int tx  = tid & 15;        // 0..15 -> 8 cols each
    int ty  = tid >> 4;        // 0..15 -> 8 rows each
    int rowBase = blockIdx.y * 128;
    int colBase = blockIdx.x * 128;

    int aRow = tid >> 1;            // 0..127
    int aCol = (tid & 1) * 4;       // 0 or 4
    int bRow = tid >> 5;            // 0..7
    int bCol = (tid & 31) * 4;      // 0..124

    const float* Aptr = A + rowBase * HDIM;
    const float* Bptr = B + colBase;

    float acc[8][8];
#pragma unroll
    for (int i = 0; i < 8; i++)
#pragma unroll
        for (int j = 0; j < 8; j++) acc[i][j] = 0.0f;

    float4 aReg = *(const float4*)(Aptr + aRow * HDIM + aCol);
    float4 bReg = *(const float4*)(Bptr + bRow * HDIM + bCol);

    for (int k0 = 0; k0 < HDIM; k0 += 8) {
        As[aCol + 0][aRow] = aReg.x;
        As[aCol + 1][aRow] = aReg.y;
        As[aCol + 2][aRow] = aReg.z;
        As[aCol + 3][aRow] = aReg.w;
        *(float4*)&Bs[bRow][bCol] = bReg;
        __syncthreads();

        if (k0 + 8 < HDIM) {  // prefetch next K-slab into registers
            aReg = *(const float4*)(Aptr + aRow * HDIM + k0 + 8 + aCol);
            bReg = *(const float4*)(Bptr + (k0 + 8 + bRow) * HDIM + bCol);
        }

#pragma unroll
        for (int k = 0; k < 8; k++) {
            float4 a0 = *(float4*)&As[k][ty * 8];
            float4 a1 = *(float4*)&As[k][ty * 8 + 4];
            float4 b0 = *(float4*)&Bs[k][tx * 8];
            float4 b1 = *(float4*)&Bs[k][tx * 8 + 4];
            float ra[8] = {a0.x, a0.y, a0.z, a0.w, a1.x, a1.y, a1.z, a1.w};
            float rb[8] = {b0.x, b0.y, b0.z, b0.w, b1.x, b1.y, b1.z, b1.w};
#pragma unroll
            for (int i = 0; i < 8; i++)
#pragma unroll
                for (int j = 0; j < 8; j++) acc[i][j] += ra[i] * rb[j];
        }
        __syncthreads();
    }

#pragma unroll
    for (int i = 0; i < 8; i++) {
        int row = rowBase + ty * 8 + i;
#pragma unroll
        for (int j = 0; j < 8; j++) {
            int col = colBase + tx * 8 + j;
            C[row * HDIM + col] = tanhf(acc[i][j] + bias[col]);
        }
    }
}

// ---------------- head: logits = h @ W_out + b_out, softmax -> y -------------
__global__ void head_kernel(const float* __restrict__ hfin,
                            const float* __restrict__ W_out,
                            const float* __restrict__ b_out) {
    int gw   = (blockIdx.x * blockDim.x + threadIdx.x) >> 5;  // one warp per row
    int lane = threadIdx.x & 31;
    if (gw >= N_PTS) return;
    const float* hr = hfin + gw * HDIM;
    float a0 = 0, a1 = 0, a2 = 0, a3 = 0, a4 = 0;
    for (int k = lane; k < HDIM; k += 32) {
        float hv = hr[k];
        const float* w = W_out + k * 5;
        a0 += hv * w[0]; a1 += hv * w[1]; a2 += hv * w[2];
        a3 += hv * w[3]; a4 += hv * w[4];
    }
#pragma unroll
    for (int off = 16; off; off >>= 1) {
        a0 += __shfl_down_sync(0xffffffffu, a0, off);
        a1 += __shfl_down_sync(0xffffffffu, a1, off);
        a2 += __shfl_down_sync(0xffffffffu, a2, off);
        a3 += __shfl_down_sync(0xffffffffu, a3, off);
        a4 += __shfl_down_sync(0xffffffffu, a4, off);
    }
    if (lane == 0) {
        a0 += b_out[0]; a1 += b_out[1]; a2 += b_out[2]; a3 += b_out[3]; a4 += b_out[4];
        float mx = fmaxf(fmaxf(fmaxf(a0, a1), fmaxf(a2, a3)), a4);
        float e0 = expf(a0 - mx), e1 = expf(a1 - mx), e2 = expf(a2 - mx);
        float e3 = expf(a3 - mx), e4 = expf(a4 - mx);
        float inv = 1.0f / (e0 + e1 + e2 + e3 + e4);
        g_y[gw * 5 + 0] = e0 * inv;
        g_y[gw * 5 + 1] = e1 * inv;
        g_y[gw * 5 + 2] = e2 * inv;
        g_y[gw * 5 + 3] = e3 * inv;
        g_y[gw * 5 + 4] = e4 * inv;
    }
}

// ---------------- dpsi = y[1:] - y[:-1] -------------------------------------
__global__ void dpsi_kernel() {
    int idx = blockIdx.x * blockDim.x + threadIdx.x;
    if (idx < NM1 * 5) g_dpsi[idx] = g_y[idx + 5] - g_y[idx];
}

// ---------------- causal Toeplitz conv: S[m] = sum_{j<=m} ws[m-j]*dpsi[j] ---
// grid (32 row-tiles, 32 j-chunks); zero-padded ws makes the diagonal exact.
__global__ void conv_kernel() {
    int rx = blockIdx.x, jy = blockIdx.y;
    if (jy > rx) return;
    __shared__ float sws[512];
    __shared__ float sd[256 * 5];
    int tid = threadIdx.x;
    int m   = rx * 256 + tid;
    int j0  = jy * 256;

    {
        int j = j0 + tid;
        if (j < NM1) {
#pragma unroll
            for (int c = 0; c < 5; c++) sd[tid * 5 + c] = g_dpsi[j * 5 + c];
        } else {
#pragma unroll
            for (int c = 0; c < 5; c++) sd[tid * 5 + c] = 0.0f;
        }
    }
    int wbase = (rx - jy) * 256 - 255;
    for (int k = tid; k < 512; k += 256) {
        int wi = wbase + k;
        sws[k] = (wi >= 0 && wi < NM1) ? g_ws[wi] : 0.0f;
    }
    __syncthreads();

    float acc0 = 0, acc1 = 0, acc2 = 0, acc3 = 0, acc4 = 0;
#pragma unroll 8
    for (int jj = 0; jj < 256; jj++) {
        float w = sws[tid + 255 - jj];
        const float* d = &sd[jj * 5];
        acc0 += w * d[0]; acc1 += w * d[1]; acc2 += w * d[2];
        acc3 += w * d[3]; acc4 += w * d[4];
    }
    if (m < NM1) {
        atomicAdd(&g_conv[m * 5 + 0], acc0);
        atomicAdd(&g_conv[m * 5 + 1], acc1);
        atomicAdd(&g_conv[m * 5 + 2], acc2);
        atomicAdd(&g_conv[m * 5 + 3], acc3);
        atomicAdd(&g_conv[m * 5 + 4], acc4);
    }
}

// ---------------- SEIRD residual + loss reduction ---------------------------
__global__ void resid_kernel() {
    __shared__ double sm[256];
    int tid = threadIdx.x;
    int row = blockIdx.x * 256 + tid;
    double local = 0.0;
    if (row < N_PTS) {
        float beta = g_par[1], sg = g_par[2], gm = g_par[3], mu = g_par[4], Cc = g_par[5];
        float ys = g_y[row * 5 + 0];
        float ye = g_y[row * 5 + 1];
        float yi = g_y[row * 5 + 2];
        float yd = g_y[row * 5 + 4];
        float inf = beta * ys * yi / (1.0f - yd);
        float f0 = -inf;
        float f1 = inf - sg * ye;
        float f2 = sg * ye - (gm + mu) * yi;
        float f3 = gm * yi;
        float f4 = mu * yi;
        float d0 = 0, d1 = 0, d2 = 0, d3 = 0, d4 = 0;
        if (row > 0) {
            const float* cv = &g_conv[(row - 1) * 5];
            d0 = Cc * cv[0]; d1 = Cc * cv[1]; d2 = Cc * cv[2];
            d3 = Cc * cv[3]; d4 = Cc * cv[4];
        }
        float r0 = d0 - f0, r1 = d1 - f1, r2 = d2 - f2, r3 = d3 - f3, r4 = d4 - f4;
        local = (double)r0 * r0 + (double)r1 * r1 + (double)r2 * r2 +
                (double)r3 * r3 + (double)r4 * r4;
    }
    sm[tid] = local;
    __syncthreads();
    for (int s2 = 128; s2; s2 >>= 1) {
        if (tid < s2) sm[tid] += sm[tid + s2];
        __syncthreads();
    }
    if (tid == 0) atomicAdd(&g_acc, sm[0]);
}

__global__ void finalize_kernel(float* __restrict__ out) {
    out[0] = (float)(g_acc / (double)(N_PTS * 5));
}

// ---------------- launch --------------------------------------------------
extern "C" void kernel_launch(void* const* d_in, const int* in_sizes, int n_in,
                              void* d_out, int out_size) {
    const float* t      = (const float*)d_in[0];
    const float* W_in   = (const float*)d_in[1];
    const float* b_in   = (const float*)d_in[2];
    const float* Wh     = (const float*)d_in[3];   // [5,512,512]
    const float* bh     = (const float*)d_in[4];   // [5,512]
    const float* W_out  = (const float*)d_in[5];   // [512,5]
    const float* b_out  = (const float*)d_in[6];
    const float* rbeta  = (const float*)d_in[7];
    const float* rsigma = (const float*)d_in[8];
    const float* rgamma = (const float*)d_in[9];
    const float* rmu    = (const float*)d_in[10];
    const float* zalpha = (const float*)d_in[11];
    float* out = (float*)d_out;

    setup_kernel<<<1, 256>>>(rbeta, rsigma, rgamma, rmu, zalpha);
    layer0_kernel<<<(N_PTS * HDIM) / 256, 256>>>(t, W_in, b_in);

    float* hin  = nullptr;
    float* hout = nullptr;
    // resolve device symbol addresses on host is not allowed inside capture via
    // cudaGetSymbolAddress? It IS allowed (no alloc, host-side query) but simpler:
    // pass through dedicated kernels using the globals directly via wrappers.
    // We instead alternate using small trampolines below.
    (void)hin; (void)hout;

    dim3 ggrid(4, 64);
    // 5 hidden layers, ping-pong g_h0 <-> g_h1 via symbol addresses.
    static float* h0_ptr = nullptr;
    static float* h1_ptr = nullptr;
    if (!h0_ptr) {
        cudaGetSymbolAddress((void**)&h0_ptr, g_h0);
        cudaGetSymbolAddress((void**)&h1_ptr, g_h1);
    }
    gemm_tanh_kernel<<<ggrid, 256>>>(h0_ptr, Wh + 0 * HDIM * HDIM, bh + 0 * HDIM, h1_ptr);
    gemm_tanh_kernel<<<ggrid, 256>>>(h1_ptr, Wh + 1 * HDIM * HDIM, bh + 1 * HDIM, h0_ptr);
    gemm_tanh_kernel<<<ggrid, 256>>>(h0_ptr, Wh + 2 * HDIM * HDIM, bh + 2 * HDIM, h1_ptr);
    gemm_tanh_kernel<<<ggrid, 256>>>(h1_ptr, Wh + 3 * HDIM * HDIM, bh + 3 * HDIM, h0_ptr);
    gemm_tanh_kernel<<<ggrid, 256>>>(h0_ptr, Wh + 4 * HDIM * HDIM, bh + 4 * HDIM, h1_ptr);

    head_kernel<<<N_PTS / 8, 256>>>(h1_ptr, W_out, b_out);
    dpsi_kernel<<<(NM1 * 5 + 255) / 256, 256>>>();
    conv_kernel<<<dim3(32, 32), 256>>>();
    resid_kernel<<<N_PTS / 256, 256>>>();
    finalize_kernel<<<1, 1>>>(out);
}

// round 2
// speedup vs baseline: 2.2013x; 2.2013x over previous
#include <cuda_runtime.h>
#include <cuda_bf16.h>
#include <math.h>
#include <stdint.h>

#define N_PTS 8192
#define HDIM  512
#define NM1   8191   // N-1
#define DEPTHM1 5

// ---------------- scratch (device globals; no allocations allowed) ----------
__device__ __align__(16) __nv_bfloat16 g_Ahi0[N_PTS * HDIM];
__device__ __align__(16) __nv_bfloat16 g_Alo0[N_PTS * HDIM];
__device__ __align__(16) __nv_bfloat16 g_Ahi1[N_PTS * HDIM];
__device__ __align__(16) __nv_bfloat16 g_Alo1[N_PTS * HDIM];
__device__ __align__(16) __nv_bfloat16 g_Whi[DEPTHM1 * HDIM * HDIM];
__device__ __align__(16) __nv_bfloat16 g_Wlo[DEPTHM1 * HDIM * HDIM];
__device__ float  g_y[N_PTS * 5];
__device__ float  g_dpsi[NM1 * 5];
__device__ float  g_ws[NM1];
__device__ float  g_conv[NM1 * 5];
__device__ float  g_par[6];   // alpha, beta, sigma, gamma, mu, C
__device__ double g_acc;

// accurate tanh: 2 MUFU (EX2 + RCP path in div) + a few FMAs, rel err ~2e-7
__device__ __forceinline__ float tanh_acc(float x) {
    float ax = fabsf(x);
    float u = __expf(-2.0f * ax);
    float t = (1.0f - u) / (1.0f + u);
    return copysignf(t, x);
}

// ---------------- setup: params + Caputo weights + zeroing ------------------
__global__ void setup_kernel(const float* __restrict__ rb, const float* __restrict__ rs,
                             const float* __restrict__ rg, const float* __restrict__ rm,
                             const float* __restrict__ za_p) {
    int tid = threadIdx.x;
    float za    = za_p[0];
    float alpha = 0.6f + 0.4f * (1.0f / (1.0f + expf(-za)));
    if (tid == 0) {
        g_par[0] = alpha;
        g_par[1] = log1pf(expf(rb[0]));   // beta
        g_par[2] = log1pf(expf(rs[0]));   // sigma
        g_par[3] = log1pf(expf(rg[0]));   // gamma
        g_par[4] = log1pf(expf(rm[0]));   // mu
        g_par[5] = powf(0.1f, -alpha) / expf(lgammaf(2.0f - alpha));  // C
        g_acc    = 0.0;
    }
    double ex = 1.0 - (double)alpha;
    for (int r = tid; r < NM1; r += blockDim.x) {
        double w = pow((double)(r + 1), ex);
        if (r > 0) w -= pow((double)r, ex);
        g_ws[r] = (float)w;
    }
    for (int i = tid; i < NM1 * 5; i += blockDim.x) g_conv[i] = 0.0f;
}

// ---------------- split weights into bf16 hi/lo ------------------------------
__global__ void wsplit_kernel(const float* __restrict__ W) {
    int i = blockIdx.x * 256 + threadIdx.x;
    if (i < DEPTHM1 * HDIM * HDIM) {
        float w = W[i];
        __nv_bfloat16 h = __float2bfloat16(w);
        g_Whi[i] = h;
        g_Wlo[i] = __float2bfloat16(w - __bfloat162float(h));
    }
}

// ---------------- layer 0: h = tanh(t * W_in + b_in) -> hi/lo ---------------
__global__ void layer0_kernel(const float* __restrict__ t,
                              const float* __restrict__ W_in,
                              const float* __restrict__ b_in) {
    int idx = blockIdx.x * blockDim.x + threadIdx.x;
    if (idx >= N_PTS * HDIM) return;
    int i = idx >> 9;
    int j = idx & (HDIM - 1);
    float h = tanh_acc(t[i] * W_in[j] + b_in[j]);
    __nv_bfloat16 hi = __float2bfloat16(h);
    g_Ahi0[idx] = hi;
    g_Alo0[idx] = __float2bfloat16(h - __bfloat162float(hi));
}

// ---------------- tensor-core GEMM (bf16x3) + bias + tanh -------------------
// C[8192,512] = tanh(A*B + bias); A as hi/lo bf16, B as hi/lo bf16 [k][n].
// Block tile 64m x 128n, BK=16, 8 warps (2 m-groups x 4 n-groups, warp 32x32).
#define STAGE_BYTES 12288   // A_hi 2K | A_lo 2K | B_hi 4K | B_lo 4K

#define LDSM4(r, addr) asm volatile( \
    "ldmatrix.sync.aligned.m8n8.x4.shared.b16 {%0,%1,%2,%3}, [%4];" \
    : "=r"(r[0]), "=r"(r[1]), "=r"(r[2]), "=r"(r[3]) : "r"(addr))

#define LDSM4T(r, addr) asm volatile( \
    "ldmatrix.sync.aligned.m8n8.x4.trans.shared.b16 {%0,%1,%2,%3}, [%4];" \
    : "=r"(r[0]), "=r"(r[1]), "=r"(r[2]), "=r"(r[3]) : "r"(addr))

#define MMA16816(d, a, b0, b1) asm volatile( \
    "mma.sync.aligned.m16n8k16.row.col.f32.bf16.bf16.f32 " \
    "{%0,%1,%2,%3},{%4,%5,%6,%7},{%8,%9},{%0,%1,%2,%3};" \
    : "+f"(d[0]), "+f"(d[1]), "+f"(d[2]), "+f"(d[3]) \
    : "r"(a[0]), "r"(a[1]), "r"(a[2]), "r"(a[3]), "r"(b0), "r"(b1))

__device__ __forceinline__ void cp16(uint32_t dst, const void* src) {
    asm volatile("cp.async.cg.shared.global [%0], [%1], 16;" :: "r"(dst), "l"(src));
}

__global__ __launch_bounds__(256, 2)
void gemm_mma_kernel(const __nv_bfloat16* __restrict__ Ahi, const __nv_bfloat16* __restrict__ Alo,
                     const __nv_bfloat16* __restrict__ Bhi, const __nv_bfloat16* __restrict__ Blo,
                     const float* __restrict__ bias,
                     __nv_bfloat16* __restrict__ Chi, __nv_bfloat16* __restrict__ Clo) {
    __shared__ __align__(128) unsigned char smem[2 * STAGE_BYTES];
    const int tid  = threadIdx.x;
    const int lane = tid & 31;
    const int wid  = tid >> 5;
    const int wm   = wid & 1;     // 0..1 -> m offset 32*wm
    const int wn   = wid >> 1;    // 0..3 -> n offset 32*wn
    const int rowBase = blockIdx.y * 64;
    const int colBase = blockIdx.x * 128;

    const uint32_t smemBase = (uint32_t)__cvta_generic_to_shared(smem);

    // ---- prefetch source/dest precompute ----
    // A: threads 0-127 load A_hi, 128-255 load A_lo. row=(t&127)>>1, kq=(t&1)*8
    const int arow = (tid & 127) >> 1;
    const int akq  = (tid & 1) * 8;
    const __nv_bfloat16* aSrc = ((tid < 128) ? Ahi : Alo) + (rowBase + arow) * HDIM + akq;
    const uint32_t aDst = (uint32_t)((tid < 128) ? 0 : 2048) + arow * 32 +
                          ((((uint32_t)(akq >> 3)) ^ ((arow >> 2) & 1)) << 4);
    // B: k=t>>4 (0..15), nq=(t&15)*8
    const int bk = tid >> 4;
    const int bnq = (tid & 15) * 8;
    const __nv_bfloat16* bhSrc = Bhi + bk * HDIM + colBase + bnq;
    const __nv_bfloat16* blSrc = Blo + bk * HDIM + colBase + bnq;
    const uint32_t bDst = 4096u + bk * 256 + ((((uint32_t)(bnq >> 3)) ^ (bk & 7)) << 4);

    float acc[2][4][4];
#pragma unroll
    for (int i = 0; i < 2; i++)
#pragma unroll
        for (int j = 0; j < 4; j++)
#pragma unroll
            for (int r = 0; r < 4; r++) acc[i][j][r] = 0.0f;

    // prologue: prefetch stage 0
    {
        uint32_t st = smemBase;
        cp16(st + aDst, aSrc);
        cp16(st + bDst, bhSrc);
        cp16(st + bDst + 4096, blSrc);
        asm volatile("cp.async.commit_group;");
    }

#pragma unroll 2
    for (int s = 0; s < 32; s++) {
        if (s < 31) {
            uint32_t st = smemBase + ((s + 1) & 1) * STAGE_BYTES;
            cp16(st + aDst, aSrc + ((s + 1) << 4));
            cp16(st + bDst, bhSrc + ((size_t)(s + 1) << 13));
            cp16(st + bDst + 4096, blSrc + ((size_t)(s + 1) << 13));
            asm volatile("cp.async.commit_group;");
            asm volatile("cp.async.wait_group 1;");
        } else {
            asm volatile("cp.async.wait_group 0;");
        }
        __syncthreads();

        const uint32_t st = smemBase + (s & 1) * STAGE_BYTES;
        uint32_t a_hi[2][4], a_lo[2][4];
#pragma unroll
        for (int i = 0; i < 2; i++) {
            int r = wm * 32 + i * 16 + (lane & 15);
            uint32_t c = ((uint32_t)(lane >> 4)) ^ ((r >> 2) & 1);
            uint32_t addr = st + r * 32 + (c << 4);
            LDSM4(a_hi[i], addr);
            LDSM4(a_lo[i], addr + 2048);
        }
        uint32_t b_hi[2][4], b_lo[2][4];
#pragma unroll
        for (int j = 0; j < 2; j++) {
            int kr = lane & 15;
            uint32_t c = ((uint32_t)(wn * 4 + j * 2 + (lane >> 4))) ^ (kr & 7);
            uint32_t addr = st + 4096u + kr * 256 + (c << 4);
            LDSM4T(b_hi[j], addr);
            LDSM4T(b_lo[j], addr + 4096);
        }
#pragma unroll
        for (int i = 0; i < 2; i++) {
#pragma unroll
            for (int j = 0; j < 2; j++) {
                MMA16816(acc[i][2 * j],     a_hi[i], b_hi[j][0], b_hi[j][1]);
                MMA16816(acc[i][2 * j + 1], a_hi[i], b_hi[j][2], b_hi[j][3]);
                MMA16816(acc[i][2 * j],     a_hi[i], b_lo[j][0], b_lo[j][1]);
                MMA16816(acc[i][2 * j + 1], a_hi[i], b_lo[j][2], b_lo[j][3]);
                MMA16816(acc[i][2 * j],     a_lo[i], b_hi[j][0], b_hi[j][1]);
                MMA16816(acc[i][2 * j + 1], a_lo[i], b_hi[j][2], b_hi[j][3]);
            }
        }
        __syncthreads();
    }

    // ---- epilogue: bias + tanh + split to hi/lo bf16 ----
#pragma unroll
    for (int i = 0; i < 2; i++) {
        int r0 = rowBase + wm * 32 + i * 16 + (lane >> 2);
#pragma unroll
        for (int jj = 0; jj < 4; jj++) {
            int c0 = colBase + wn * 32 + jj * 8 + (lane & 3) * 2;
            float bv0 = bias[c0], bv1 = bias[c0 + 1];
#pragma unroll
            for (int half = 0; half < 2; half++) {
                int r = r0 + half * 8;
                float x0 = acc[i][jj][2 * half + 0] + bv0;
                float x1 = acc[i][jj][2 * half + 1] + bv1;
                float t0 = tanh_acc(x0);
                float t1 = tanh_acc(x1);
                __nv_bfloat16 h0 = __float2bfloat16(t0);
                __nv_bfloat16 h1 = __float2bfloat16(t1);
                __nv_bfloat162 hv; hv.x = h0; hv.y = h1;
                __nv_bfloat162 lv;
                lv.x = __float2bfloat16(t0 - __bfloat162float(h0));
                lv.y = __float2bfloat16(t1 - __bfloat162float(h1));
                *(__nv_bfloat162*)(Chi + (size_t)r * HDIM + c0) = hv;
                *(__nv_bfloat162*)(Clo + (size_t)r * HDIM + c0) = lv;
            }
        }
    }
}

// ---------------- head: logits = h @ W_out + b_out, softmax -> y -------------
__global__ void head_kernel(const __nv_bfloat16* __restrict__ hhi,
                            const __nv_bfloat16* __restrict__ hlo,
                            const float* __restrict__ W_out,
                            const float* __restrict__ b_out) {
    int gw   = (blockIdx.x * blockDim.x + threadIdx.x) >> 5;
    int lane = threadIdx.x & 31;
    if (gw >= N_PTS) return;
    const __nv_bfloat16* hr = hhi + (size_t)gw * HDIM;
    const __nv_bfloat16* lr = hlo + (size_t)gw * HDIM;
    float a0 = 0, a1 = 0, a2 = 0, a3 = 0, a4 = 0;
    for (int k = lane; k < HDIM; k += 32) {
        float hv = __bfloat162float(hr[k]) + __bfloat162float(lr[k]);
        const float* w = W_out + k * 5;
        a0 += hv * w[0]; a1 += hv * w[1]; a2 += hv * w[2];
        a3 += hv * w[3]; a4 += hv * w[4];
    }
#pragma unroll
    for (int off = 16; off; off >>= 1) {
        a0 += __shfl_down_sync(0xffffffffu, a0, off);
        a1 += __shfl_down_sync(0xffffffffu, a1, off);
        a2 += __shfl_down_sync(0xffffffffu, a2, off);
        a3 += __shfl_down_sync(0xffffffffu, a3, off);
        a4 += __shfl_down_sync(0xffffffffu, a4, off);
    }
    if (lane == 0) {
        a0 += b_out[0]; a1 += b_out[1]; a2 += b_out[2]; a3 += b_out[3]; a4 += b_out[4];
        float mx = fmaxf(fmaxf(fmaxf(a0, a1), fmaxf(a2, a3)), a4);
        float e0 = expf(a0 - mx), e1 = expf(a1 - mx), e2 = expf(a2 - mx);
        float e3 = expf(a3 - mx), e4 = expf(a4 - mx);
        float inv = 1.0f / (e0 + e1 + e2 + e3 + e4);
        g_y[gw * 5 + 0] = e0 * inv;
        g_y[gw * 5 + 1] = e1 * inv;
        g_y[gw * 5 + 2] = e2 * inv;
        g_y[gw * 5 + 3] = e3 * inv;
        g_y[gw * 5 + 4] = e4 * inv;
    }
}

// ---------------- dpsi = y[1:] - y[:-1] -------------------------------------
__global__ void dpsi_kernel() {
    int idx = blockIdx.x * blockDim.x + threadIdx.x;
    if (idx < NM1 * 5) g_dpsi[idx] = g_y[idx + 5] - g_y[idx];
}

// ---------------- causal Toeplitz conv --------------------------------------
__global__ void conv_kernel() {
    int rx = blockIdx.x, jy = blockIdx.y;
    if (jy > rx) return;
    __shared__ float sws[512];
    __shared__ float sd[256 * 5];
    int tid = threadIdx.x;
    int m   = rx * 256 + tid;
    int j0  = jy * 256;

    {
        int j = j0 + tid;
        if (j < NM1) {
#pragma unroll
            for (int c = 0; c < 5; c++) sd[tid * 5 + c] = g_dpsi[j * 5 + c];
        } else {
#pragma unroll
            for (int c = 0; c < 5; c++) sd[tid * 5 + c] = 0.0f;
        }
    }
    int wbase = (rx - jy) * 256 - 255;
    for (int k = tid; k < 512; k += 256) {
        int wi = wbase + k;
        sws[k] = (wi >= 0 && wi < NM1) ? g_ws[wi] : 0.0f;
    }
    __syncthreads();

    float acc0 = 0, acc1 = 0, acc2 = 0, acc3 = 0, acc4 = 0;
#pragma unroll 8
    for (int jj = 0; jj < 256; jj++) {
        float w = sws[tid + 255 - jj];
        const float* d = &sd[jj * 5];
        acc0 += w * d[0]; acc1 += w * d[1]; acc2 += w * d[2];
        acc3 += w * d[3]; acc4 += w * d[4];
    }
    if (m < NM1) {
        atomicAdd(&g_conv[m * 5 + 0], acc0);
        atomicAdd(&g_conv[m * 5 + 1], acc1);
        atomicAdd(&g_conv[m * 5 + 2], acc2);
        atomicAdd(&g_conv[m * 5 + 3], acc3);
        atomicAdd(&g_conv[m * 5 + 4], acc4);
    }
}

// ---------------- SEIRD residual + loss reduction ---------------------------
__global__ void resid_kernel() {
    __shared__ double sm[256];
    int tid = threadIdx.x;
    int row = blockIdx.x * 256 + tid;
    double local = 0.0;
    if (row < N_PTS) {
        float beta = g_par[1], sg = g_par[2], gm = g_par[3], mu = g_par[4], Cc = g_par[5];
        float ys = g_y[row * 5 + 0];
        float ye = g_y[row * 5 + 1];
        float yi = g_y[row * 5 + 2];
        float yd = g_y[row * 5 + 4];
        float inf = beta * ys * yi / (1.0f - yd);
        float f0 = -inf;
        float f1 = inf - sg * ye;
        float f2 = sg * ye - (gm + mu) * yi;
        float f3 = gm * yi;
        float f4 = mu * yi;
        float d0 = 0, d1 = 0, d2 = 0, d3 = 0, d4 = 0;
        if (row > 0) {
            const float* cv = &g_conv[(row - 1) * 5];
            d0 = Cc * cv[0]; d1 = Cc * cv[1]; d2 = Cc * cv[2];
            d3 = Cc * cv[3]; d4 = Cc * cv[4];
        }
        float r0 = d0 - f0, r1 = d1 - f1, r2 = d2 - f2, r3 = d3 - f3, r4 = d4 - f4;
        local = (double)r0 * r0 + (double)r1 * r1 + (double)r2 * r2 +
                (double)r3 * r3 + (double)r4 * r4;
    }
    sm[tid] = local;
    __syncthreads();
    for (int s2 = 128; s2; s2 >>= 1) {
        if (tid < s2) sm[tid] += sm[tid + s2];
        __syncthreads();
    }
    if (tid == 0) atomicAdd(&g_acc, sm[0]);
}

__global__ void finalize_kernel(float* __restrict__ out) {
    out[0] = (float)(g_acc / (double)(N_PTS * 5));
}

// ---------------- launch ----------------------------------------------------
extern "C" void kernel_launch(void* const* d_in, const int* in_sizes, int n_in,
                              void* d_out, int out_size) {
    const float* t      = (const float*)d_in[0];
    const float* W_in   = (const float*)d_in[1];
    const float* b_in   = (const float*)d_in[2];
    const float* Wh     = (const float*)d_in[3];   // [5,512,512]
    const float* bh     = (const float*)d_in[4];   // [5,512]
    const float* W_out  = (const float*)d_in[5];   // [512,5]
    const float* b_out  = (const float*)d_in[6];
    const float* rbeta  = (const float*)d_in[7];
    const float* rsigma = (const float*)d_in[8];
    const float* rgamma = (const float*)d_in[9];
    const float* rmu    = (const float*)d_in[10];
    const float* zalpha = (const float*)d_in[11];
    float* out = (float*)d_out;

    static __nv_bfloat16 *ahi0 = nullptr, *alo0 = nullptr, *ahi1 = nullptr, *alo1 = nullptr;
    static __nv_bfloat16 *whi = nullptr, *wlo = nullptr;
    if (!ahi0) {
        cudaGetSymbolAddress((void**)&ahi0, g_Ahi0);
        cudaGetSymbolAddress((void**)&alo0, g_Alo0);
        cudaGetSymbolAddress((void**)&ahi1, g_Ahi1);
        cudaGetSymbolAddress((void**)&alo1, g_Alo1);
        cudaGetSymbolAddress((void**)&whi, g_Whi);
        cudaGetSymbolAddress((void**)&wlo, g_Wlo);
    }

    setup_kernel<<<1, 256>>>(rbeta, rsigma, rgamma, rmu, zalpha);
    wsplit_kernel<<<(DEPTHM1 * HDIM * HDIM + 255) / 256, 256>>>(Wh);
    layer0_kernel<<<(N_PTS * HDIM) / 256, 256>>>(t, W_in, b_in);

    dim3 ggrid(4, 128);   // (512/128, 8192/64)
    const int WW = HDIM * HDIM;
    gemm_mma_kernel<<<ggrid, 256>>>(ahi0, alo0, whi + 0 * WW, wlo + 0 * WW, bh + 0 * HDIM, ahi1, alo1);
    gemm_mma_kernel<<<ggrid, 256>>>(ahi1, alo1, whi + 1 * WW, wlo + 1 * WW, bh + 1 * HDIM, ahi0, alo0);
    gemm_mma_kernel<<<ggrid, 256>>>(ahi0, alo0, whi + 2 * WW, wlo + 2 * WW, bh + 2 * HDIM, ahi1, alo1);
    gemm_mma_kernel<<<ggrid, 256>>>(ahi1, alo1, whi + 3 * WW, wlo + 3 * WW, bh + 3 * HDIM, ahi0, alo0);
    gemm_mma_kernel<<<ggrid, 256>>>(ahi0, alo0, whi + 4 * WW, wlo + 4 * WW, bh + 4 * HDIM, ahi1, alo1);

    head_kernel<<<N_PTS / 8, 256>>>(ahi1, alo1, W_out, b_out);
    dpsi_kernel<<<(NM1 * 5 + 255) / 256, 256>>>();
    conv_kernel<<<dim3(32, 32), 256>>>();
    resid_kernel<<<N_PTS / 256, 256>>>();
    finalize_kernel<<<1, 1>>>(out);
}